// round 9
// baseline (speedup 1.0000x reference)
#include <cuda_runtime.h>
#include <cuda_bf16.h>
#include <math.h>

#define TPB 256

// ---------------- scratch (static device globals; no allocation) ----------------
// tmpA: pass-1 output, max 4*3*64*64*16 = 786432 floats per tensor
// tmpB: pass-2 output, max 4*3*64*16*16 = 196608 floats per tensor
__device__ float g_tmpA[2][786432];
__device__ float g_tmpB[2][196608];
__device__ float g_r0[2][49152];     // stage0 resized [tensor][B=4][3][4096]
__device__ float g_r1[2][6144];      // stage1 resized [tensor][B=4][3][512]
__device__ unsigned long long g_k0[16384];  // stage0 argmin keys [B][N0]
__device__ unsigned long long g_k1[2048];   // stage1 argmin keys [B][N1]
__device__ double g_acc[2];          // per-stage cos sums

// device-side buffer selector (avoids any host-side symbol-address lookup)
__device__ __forceinline__ float* buf_ptr(int id, int tensor) {
    switch (id) {
        case 0:  return g_tmpA[tensor];
        case 1:  return g_tmpB[tensor];
        case 2:  return g_r0[tensor];
        default: return g_r1[tensor];
    }
}

// ---------------- init ----------------
__global__ void init_kernel() {
    int i = blockIdx.x * blockDim.x + threadIdx.x;
    if (i < 16384) g_k0[i] = ~0ULL;
    if (i < 2048)  g_k1[i] = ~0ULL;
    if (i < 2)     g_acc[i] = 0.0;
}

// ---------------- separable resize pass ----------------
// view array as [outer, L, inner]; resize L: Lin -> Lout with jax triangle
// antialias weights (kernel_scale = R = Lin/Lout, half-pixel centers,
// per-dim normalization over in-range taps). gridDim.y selects tensor
// (0 = source, 1 = target). src_id == -1 means read the external input.
__global__ void resize_pass(const float* __restrict__ ext0, const float* __restrict__ ext1,
                            int src_id, int dst_id,
                            int outer, int Lin, int Lout, int inner, int Ri)
{
    int total = outer * Lout * inner;
    int idx = blockIdx.x * blockDim.x + threadIdx.x;
    if (idx >= total) return;
    int tensor = blockIdx.y;
    const float* in = (src_id < 0) ? (tensor ? ext1 : ext0) : buf_ptr(src_id, tensor);
    float* out = buf_ptr(dst_id, tensor);

    int t   = idx % inner;
    int rem = idx / inner;
    int i   = rem % Lout;
    int o   = rem / Lout;

    const float R = (float)Ri;
    const float invR = 1.0f / R;
    float sf = (i + 0.5f) * R - 0.5f;          // sample position in input space
    int jlo = (int)floorf(sf - R) + 1;         // smallest j with w > 0
    int jhi = (int)ceilf (sf + R) - 1;         // largest  j with w > 0
    if (jlo < 0) jlo = 0;
    if (jhi > Lin - 1) jhi = Lin - 1;

    const float* src = in + (size_t)o * Lin * inner + t;
    float acc = 0.0f, wsum = 0.0f;
    for (int j = jlo; j <= jhi; ++j) {
        float w = 1.0f - fabsf((float)j - sf) * invR;
        wsum += w;
        acc = fmaf(w, src[(size_t)j * inner], acc);
    }
    out[idx] = acc / wsum;
}

// ---------------- nearest neighbor (argmin over m of squared distance) ----------------
// score = 0.5*|b|^2 - a.b  (argmin-equivalent to |a-b|^2; a^2 term constant in m)
// grid: (B, N/(TPB*NPT), mtiles). Partial argmins merged via atomicMin on a
// 64-bit key = (order-preserving float bits << 32) | m  -> lower m wins ties,
// matching jnp.argmin first-occurrence semantics.
// STAGE 0: A/B = g_r0, keys = g_k0, N = 4096. STAGE 1: g_r1 / g_k1, N = 512.
template<int STAGE, int NPT>
__global__ void nn_kernel()
{
    const int N = (STAGE == 0) ? 4096 : 512;
    const float* A  = (STAGE == 0) ? g_r0[0] : g_r1[0];
    const float* Bp = (STAGE == 0) ? g_r0[1] : g_r1[1];
    unsigned long long* keys = (STAGE == 0) ? g_k0 : g_k1;

    __shared__ float4 sB[512];
    int b  = blockIdx.x;
    int Nm = N / gridDim.z;
    int m0 = blockIdx.z * Nm;

    const float* bx = Bp + (size_t)b * 3 * N;
    for (int i = threadIdx.x; i < Nm; i += TPB) {
        int m = m0 + i;
        float x = bx[m], y = bx[N + m], z = bx[2 * N + m];
        sB[i] = make_float4(x, y, z, 0.5f * (x * x + y * y + z * z));
    }
    __syncthreads();

    const float* ax = A + (size_t)b * 3 * N;
    int nb = blockIdx.y * (TPB * NPT) + threadIdx.x;

    float px[NPT], py[NPT], pz[NPT], best[NPT];
    int bm[NPT];
#pragma unroll
    for (int k = 0; k < NPT; ++k) {
        int n = nb + k * TPB;
        px[k] = ax[n]; py[k] = ax[N + n]; pz[k] = ax[2 * N + n];
        best[k] = 3.402823466e38f; bm[k] = 0;
    }

#pragma unroll 4
    for (int i = 0; i < Nm; ++i) {
        float4 q = sB[i];
#pragma unroll
        for (int k = 0; k < NPT; ++k) {
            float s = fmaf(-px[k], q.x, q.w);
            s = fmaf(-py[k], q.y, s);
            s = fmaf(-pz[k], q.z, s);
            if (s < best[k]) { best[k] = s; bm[k] = i; }
        }
    }

#pragma unroll
    for (int k = 0; k < NPT; ++k) {
        int n = nb + k * TPB;
        unsigned u = __float_as_uint(best[k]);
        u = (u & 0x80000000u) ? ~u : (u | 0x80000000u);   // order-preserving map
        unsigned long long key = ((unsigned long long)u << 32) | (unsigned)(m0 + bm[k]);
        atomicMin(&keys[(size_t)b * N + n], key);
    }
}

// ---------------- cosine similarity + reduction ----------------
// desc layout [B][32][N]; flattened-spatial element (b,n,c) = desc[b,c,n].
template<int STAGE>
__global__ void cos_kernel(const float* __restrict__ sd, const float* __restrict__ td)
{
    const int N = (STAGE == 0) ? 4096 : 512;
    const unsigned long long* keys = (STAGE == 0) ? g_k0 : g_k1;

    int b = blockIdx.y;
    int n = blockIdx.x * TPB + threadIdx.x;
    int m = (int)(unsigned)(keys[(size_t)b * N + n] & 0xFFFFFFFFull);

    const float* s = sd + (size_t)b * 32 * N;
    const float* t = td + (size_t)b * 32 * N;
    float dot = 0.f, ns = 0.f, ng = 0.f;
#pragma unroll
    for (int c = 0; c < 32; ++c) {
        float x = s[(size_t)c * N + n];
        float y = t[(size_t)c * N + m];
        dot = fmaf(x, y, dot);
        ns  = fmaf(x, x, ns);
        ng  = fmaf(y, y, ng);
    }
    float cv = dot / (fmaxf(sqrtf(ns), 1e-8f) * fmaxf(sqrtf(ng), 1e-8f));

    // warp + block reduce, then one double atomic per block
    for (int o = 16; o > 0; o >>= 1) cv += __shfl_down_sync(0xffffffffu, cv, o);
    __shared__ float wsum[TPB / 32];
    if ((threadIdx.x & 31) == 0) wsum[threadIdx.x >> 5] = cv;
    __syncthreads();
    if (threadIdx.x < TPB / 32) {
        float v = wsum[threadIdx.x];
        for (int o = (TPB / 64); o > 0; o >>= 1) v += __shfl_down_sync(0xffu, v, o);
        if (threadIdx.x == 0) atomicAdd(&g_acc[STAGE], (double)v);
    }
}

// ---------------- finalize ----------------
__global__ void finalize_kernel(float* out) {
    double l0 = 1.0 - g_acc[0] / (4.0 * 4096.0);
    double l1 = 1.0 - g_acc[1] / (4.0 * 512.0);
    out[0] = (float)(0.5 * (l0 + l1));
}

// ---------------- launch (kernel launches ONLY; no other runtime API) ----------------
extern "C" void kernel_launch(void* const* d_in, const int* in_sizes, int n_in,
                              void* d_out, int out_size)
{
    const float* cs  = (const float*)d_in[0];  // canonical_source [4,3,64,64,64]
    const float* ct  = (const float*)d_in[1];  // canonical_target
    const float* sd0 = (const float*)d_in[2];  // src_desc0 [4,32,16,16,16]
    const float* td0 = (const float*)d_in[3];
    const float* sd1 = (const float*)d_in[4];  // src_desc1 [4,32,8,8,8]
    const float* td1 = (const float*)d_in[5];
    float* out = (float*)d_out;

    init_kernel<<<64, TPB>>>();

    // ---- stage 0 resize: 64^3 -> 16^3 (R=4), separable W,H,D ----
    // buffer ids: -1 = external input, 0 = g_tmpA, 1 = g_tmpB, 2 = g_r0, 3 = g_r1
    resize_pass<<<dim3(3072, 2), TPB>>>(cs, ct, -1, 0, 4 * 3 * 64 * 64, 64, 16, 1, 4);
    resize_pass<<<dim3(768, 2),  TPB>>>(cs, ct,  0, 1, 4 * 3 * 64,      64, 16, 16, 4);
    resize_pass<<<dim3(192, 2),  TPB>>>(cs, ct,  1, 2, 12,              64, 16, 256, 4);

    // ---- stage 1 resize: 64^3 -> 8^3 (R=8) ----
    resize_pass<<<dim3(1536, 2), TPB>>>(cs, ct, -1, 0, 4 * 3 * 64 * 64, 64, 8, 1, 8);
    resize_pass<<<dim3(192, 2),  TPB>>>(cs, ct,  0, 1, 4 * 3 * 64,      64, 8, 8, 8);
    resize_pass<<<dim3(24, 2),   TPB>>>(cs, ct,  1, 3, 12,              64, 8, 64, 8);

    // ---- nearest neighbor ----
    // stage0: N=4096, NPT=4 -> grid.y = 4096/1024 = 4; 16 m-tiles (Nm=256)
    nn_kernel<0, 4><<<dim3(4, 4, 16), TPB>>>();
    // stage1: N=512, NPT=2 -> grid.y = 1; 8 m-tiles (Nm=64)
    nn_kernel<1, 2><<<dim3(4, 1, 8), TPB>>>();

    // ---- cosine + reduce ----
    cos_kernel<0><<<dim3(16, 4), TPB>>>(sd0, td0);
    cos_kernel<1><<<dim3(2, 4),  TPB>>>(sd1, td1);

    finalize_kernel<<<1, 1>>>(out);
}

// round 10
// speedup vs baseline: 1.2794x; 1.2794x over previous
#include <cuda_runtime.h>
#include <cuda_bf16.h>
#include <math.h>

#define TPB 256

// ---------------- scratch (static device globals; no allocation) ----------------
// Separate buffers per stage so stage0/stage1 pipelines run concurrently.
__device__ float g_t0A[2][786432];   // stage0 pass1 out [tensor][4*3*64*64, 16]
__device__ float g_t0B[2][196608];   // stage0 pass2 out [tensor][4*3*64, 16, 16]
__device__ float g_r0[2][49152];     // stage0 resized  [tensor][B=4][3][4096]
__device__ float g_t1A[2][393216];   // stage1 pass1 out [tensor][4*3*64*64, 8]
__device__ float g_t1B[2][49152];    // stage1 pass2 out [tensor][4*3*64, 8, 8]
__device__ float g_r1[2][6144];      // stage1 resized  [tensor][B=4][3][512]
__device__ unsigned long long g_k0[16384];  // stage0 argmin keys [B][4096]
__device__ unsigned long long g_k1[2048];   // stage1 argmin keys [B][512]
__device__ double g_acc[2];          // per-stage cos sums
__device__ unsigned g_done;          // cos completion counter (self-resetting)

// ---------------- fused separable resize pass ----------------
// gridDim.y = 4: y&1 selects tensor (0=src ext, 1=tgt ext), y>>1 selects stage.
// View array as [outer, 64, inner]; resize 64 -> Lout with jax triangle
// antialias weights (kernel_scale R = 64/Lout, half-pixel centers, per-dim
// normalization over in-range taps). PASS=1 also initializes keys/acc.
template<int PASS>
__global__ void resize_fused(const float* __restrict__ ext0,
                             const float* __restrict__ ext1)
{
    int tensor = blockIdx.y & 1;
    int stage  = blockIdx.y >> 1;

    if (PASS == 1 && blockIdx.y == 0) {       // fold init into pass 1
        int ii = blockIdx.x * TPB + threadIdx.x;
        if (ii < 16384) g_k0[ii] = ~0ULL;
        if (ii < 2048)  g_k1[ii] = ~0ULL;
        if (ii < 2)     g_acc[ii] = 0.0;
        if (ii == 0)    g_done = 0u;
    }

    int outer, Lout, inner, Ri;
    const float* in; float* out;
    if (PASS == 1) {
        outer = 4 * 3 * 64 * 64; inner = 1;
        in = tensor ? ext1 : ext0;
        if (stage == 0) { Lout = 16; Ri = 4; out = g_t0A[tensor]; }
        else            { Lout = 8;  Ri = 8; out = g_t1A[tensor]; }
    } else if (PASS == 2) {
        outer = 4 * 3 * 64;
        if (stage == 0) { Lout = 16; Ri = 4; inner = 16; in = g_t0A[tensor]; out = g_t0B[tensor]; }
        else            { Lout = 8;  Ri = 8; inner = 8;  in = g_t1A[tensor]; out = g_t1B[tensor]; }
    } else {
        outer = 12;
        if (stage == 0) { Lout = 16; Ri = 4; inner = 256; in = g_t0B[tensor]; out = g_r0[tensor]; }
        else            { Lout = 8;  Ri = 8; inner = 64;  in = g_t1B[tensor]; out = g_r1[tensor]; }
    }
    const int Lin = 64;

    int total = outer * Lout * inner;
    int idx = blockIdx.x * TPB + threadIdx.x;
    if (idx >= total) return;

    int t   = idx % inner;
    int rem = idx / inner;
    int i   = rem % Lout;
    int o   = rem / Lout;

    const float R = (float)Ri;
    const float invR = 1.0f / R;
    float sf = (i + 0.5f) * R - 0.5f;          // sample position in input space
    int jlo = (int)floorf(sf - R) + 1;         // smallest j with w > 0
    int jhi = (int)ceilf (sf + R) - 1;         // largest  j with w > 0
    if (jlo < 0) jlo = 0;
    if (jhi > Lin - 1) jhi = Lin - 1;

    const float* src = in + (size_t)o * Lin * inner + t;
    float acc = 0.0f, wsum = 0.0f;
    for (int j = jlo; j <= jhi; ++j) {
        float w = 1.0f - fabsf((float)j - sf) * invR;
        wsum += w;
        acc = fmaf(w, src[(size_t)j * inner], acc);
    }
    out[idx] = acc / wsum;
}

// ---------------- nearest neighbor (argmin over m of squared distance) ----------------
// score = 0.5*|b|^2 - a.b  (argmin-equivalent to |a-b|^2; a^2 term constant in m).
// Partial argmins over m-tiles merged via atomicMin on 64-bit key
// (order-preserving float bits << 32) | m -> lower m wins ties, matching
// jnp.argmin first-occurrence semantics.
template<int N, int NPT, int NM>
__device__ __forceinline__ void nn_body(const float* __restrict__ A,
                                        const float* __restrict__ Bp,
                                        unsigned long long* __restrict__ keys,
                                        int m0, int ytile, float4* sB)
{
    int b = blockIdx.x;
    const float* bx = Bp + (size_t)b * 3 * N;
    for (int i = threadIdx.x; i < NM; i += TPB) {
        int m = m0 + i;
        float x = bx[m], y = bx[N + m], z = bx[2 * N + m];
        sB[i] = make_float4(x, y, z, 0.5f * (x * x + y * y + z * z));
    }
    __syncthreads();

    const float* ax = A + (size_t)b * 3 * N;
    int nb = ytile * (TPB * NPT) + threadIdx.x;

    float px[NPT], py[NPT], pz[NPT], best[NPT];
    int bm[NPT];
#pragma unroll
    for (int k = 0; k < NPT; ++k) {
        int n = nb + k * TPB;
        px[k] = ax[n]; py[k] = ax[N + n]; pz[k] = ax[2 * N + n];
        best[k] = 3.402823466e38f; bm[k] = 0;
    }

#pragma unroll 4
    for (int i = 0; i < NM; ++i) {
        float4 q = sB[i];
#pragma unroll
        for (int k = 0; k < NPT; ++k) {
            float s = fmaf(-px[k], q.x, q.w);
            s = fmaf(-py[k], q.y, s);
            s = fmaf(-pz[k], q.z, s);
            if (s < best[k]) { best[k] = s; bm[k] = i; }
        }
    }

#pragma unroll
    for (int k = 0; k < NPT; ++k) {
        int n = nb + k * TPB;
        unsigned u = __float_as_uint(best[k]);
        u = (u & 0x80000000u) ? ~u : (u | 0x80000000u);   // order-preserving map
        unsigned long long key = ((unsigned long long)u << 32) | (unsigned)(m0 + bm[k]);
        atomicMin(&keys[(size_t)b * N + n], key);
    }
}

// grid (4, 4, 24): z<16 -> stage0 (N=4096, NPT=4, Nm=256, 16 m-tiles);
// z>=16 -> stage1 (N=512, NPT=2, Nm=64, 8 m-tiles; only y==0 active).
__global__ void nn_fused()
{
    __shared__ float4 sB[256];
    if (blockIdx.z < 16) {
        nn_body<4096, 4, 256>(g_r0[0], g_r0[1], g_k0,
                              (int)blockIdx.z * 256, blockIdx.y, sB);
    } else {
        if (blockIdx.y != 0) return;
        nn_body<512, 2, 64>(g_r1[0], g_r1[1], g_k1,
                            ((int)blockIdx.z - 16) * 64, 0, sB);
    }
}

// ---------------- cosine similarity + reduction + in-kernel finalize ----------------
// desc layout [B][32][N]; flattened-spatial element (b,n,c) = desc[b,c,n].
template<int N>
__device__ __forceinline__ float cos_body(const float* __restrict__ sd,
                                          const float* __restrict__ td,
                                          const unsigned long long* __restrict__ keys,
                                          int xblk)
{
    int b = blockIdx.y;
    int n = xblk * TPB + threadIdx.x;
    int m = (int)(unsigned)(keys[(size_t)b * N + n] & 0xFFFFFFFFull);

    const float* s = sd + (size_t)b * 32 * N;
    const float* t = td + (size_t)b * 32 * N;
    float dot = 0.f, ns = 0.f, ng = 0.f;
#pragma unroll
    for (int c = 0; c < 32; ++c) {
        float x = s[(size_t)c * N + n];
        float y = t[(size_t)c * N + m];
        dot = fmaf(x, y, dot);
        ns  = fmaf(x, x, ns);
        ng  = fmaf(y, y, ng);
    }
    return dot / (fmaxf(sqrtf(ns), 1e-8f) * fmaxf(sqrtf(ng), 1e-8f));
}

// grid (18, 4): x<16 -> stage0 (N=4096), x in {16,17} -> stage1 (N=512).
// 72 blocks total; the last one to finish computes the final scalar.
__global__ void cos_fused(const float* __restrict__ sd0, const float* __restrict__ td0,
                          const float* __restrict__ sd1, const float* __restrict__ td1,
                          float* __restrict__ out)
{
    int xb = blockIdx.x;
    int stage = (xb < 16) ? 0 : 1;
    float cv = (stage == 0) ? cos_body<4096>(sd0, td0, g_k0, xb)
                            : cos_body<512>(sd1, td1, g_k1, xb - 16);

    // warp + block reduce, one double atomic per block
    for (int o = 16; o > 0; o >>= 1) cv += __shfl_down_sync(0xffffffffu, cv, o);
    __shared__ float wsum[TPB / 32];
    if ((threadIdx.x & 31) == 0) wsum[threadIdx.x >> 5] = cv;
    __syncthreads();
    if (threadIdx.x < TPB / 32) {
        float v = wsum[threadIdx.x];
        for (int o = (TPB / 64); o > 0; o >>= 1) v += __shfl_down_sync(0xffu, v, o);
        if (threadIdx.x == 0) {
            atomicAdd(&g_acc[stage], (double)v);
            __threadfence();
            unsigned t = atomicAdd(&g_done, 1u);
            if (t == 71u) {                       // last block: finalize
                double a0 = atomicAdd(&g_acc[0], 0.0);   // coherent reads
                double a1 = atomicAdd(&g_acc[1], 0.0);
                double l0 = 1.0 - a0 / (4.0 * 4096.0);
                double l1 = 1.0 - a1 / (4.0 * 512.0);
                out[0] = (float)(0.5 * (l0 + l1));
                g_done = 0u;                       // reset for next graph replay
            }
        }
    }
}

// ---------------- launch (kernel launches ONLY) ----------------
extern "C" void kernel_launch(void* const* d_in, const int* in_sizes, int n_in,
                              void* d_out, int out_size)
{
    const float* cs  = (const float*)d_in[0];  // canonical_source [4,3,64,64,64]
    const float* ct  = (const float*)d_in[1];  // canonical_target
    const float* sd0 = (const float*)d_in[2];  // src_desc0 [4,32,16,16,16]
    const float* td0 = (const float*)d_in[3];
    const float* sd1 = (const float*)d_in[4];  // src_desc1 [4,32,8,8,8]
    const float* td1 = (const float*)d_in[5];
    float* out = (float*)d_out;

    // pass1: stage0 needs 3072 blocks/tensor, stage1 1536 (extra blocks exit)
    resize_fused<1><<<dim3(3072, 4), TPB>>>(cs, ct);
    // pass2: stage0 768, stage1 192
    resize_fused<2><<<dim3(768, 4), TPB>>>(cs, ct);
    // pass3: stage0 192, stage1 24
    resize_fused<3><<<dim3(192, 4), TPB>>>(cs, ct);

    nn_fused<<<dim3(4, 4, 24), TPB>>>();

    cos_fused<<<dim3(18, 4), TPB>>>(sd0, td0, sd1, td1, out);
}

// round 11
// speedup vs baseline: 1.3554x; 1.0594x over previous
#include <cuda_runtime.h>
#include <cuda_bf16.h>
#include <math.h>

#define TPB  256
#define NBLK 592                      // 4 blocks/SM * 148 SMs -> all resident
#define GT   (NBLK * TPB)

// ---------------- scratch (static device globals; no allocation) ----------------
__device__ float g_t0A[2][786432];   // stage0 pass1 out
__device__ float g_t0B[2][196608];   // stage0 pass2 out
__device__ float g_r0[2][49152];     // stage0 resized [tensor][B=4][3][4096]
__device__ float g_t1A[2][393216];   // stage1 pass1 out
__device__ float g_t1B[2][49152];    // stage1 pass2 out
__device__ float g_r1[2][6144];      // stage1 resized [tensor][B=4][3][512]
__device__ unsigned long long g_k0[16384];  // stage0 argmin keys [B][4096]
__device__ unsigned long long g_k1[2048];   // stage1 argmin keys [B][512]
__device__ double g_acc[2];          // per-stage cos sums
__device__ unsigned g_bar;           // barrier arrival counter (self-resets)
__device__ unsigned g_gen;           // barrier generation (monotone across replays)

// ---------------- grid-wide barrier (all NBLK blocks resident by construction) --
__device__ __forceinline__ void grid_sync() {
    __syncthreads();
    if (threadIdx.x == 0) {
        __threadfence();
        unsigned gen = atomicAdd(&g_gen, 0u);
        if (atomicAdd(&g_bar, 1u) == NBLK - 1u) {
            atomicExch(&g_bar, 0u);
            __threadfence();
            atomicAdd(&g_gen, 1u);                // release
        } else {
            while (atomicAdd(&g_gen, 0u) == gen) { }
        }
        __threadfence();
    }
    __syncthreads();
}

// ---------------- separable resize element (jax triangle antialias) -------------
// view as [outer, 64, inner]; resize 64 -> Lout. kernel_scale R = 64/Lout,
// half-pixel centers, per-dim normalization over in-range taps.
__device__ __forceinline__ void resize_elem(const float* __restrict__ in,
                                            float* __restrict__ out,
                                            int Lout, int inner,
                                            float R, float invR, int idx)
{
    int t   = idx % inner;
    int rem = idx / inner;
    int i   = rem % Lout;
    int o   = rem / Lout;

    float sf = (i + 0.5f) * R - 0.5f;
    int jlo = (int)floorf(sf - R) + 1;
    int jhi = (int)ceilf (sf + R) - 1;
    if (jlo < 0) jlo = 0;
    if (jhi > 63) jhi = 63;

    const float* src = in + (size_t)o * 64 * inner + t;
    float acc = 0.0f, wsum = 0.0f;
    for (int j = jlo; j <= jhi; ++j) {
        float w = 1.0f - fabsf((float)j - sf) * invR;
        wsum += w;
        acc = fmaf(w, src[(size_t)j * inner], acc);
    }
    out[idx] = acc / wsum;
}

// ---------------- nearest neighbor unit ----------------------------------------
// score = 0.5*|b|^2 - a.b (argmin-equivalent to |a-b|^2). Partial argmins over
// m-tiles merged via atomicMin on key (sortable float bits << 32) | m; lower m
// wins ties -> jnp.argmin first-occurrence semantics.
template<int N, int NPT, int NM>
__device__ __forceinline__ void nn_unit(const float* __restrict__ A,
                                        const float* __restrict__ Bp,
                                        unsigned long long* __restrict__ keys,
                                        int b, int ytile, int mtile, float4* sB)
{
    int m0 = mtile * NM;
    const float* bx = Bp + (size_t)b * 3 * N;
    for (int i = threadIdx.x; i < NM; i += TPB) {
        int m = m0 + i;
        float x = bx[m], y = bx[N + m], z = bx[2 * N + m];
        sB[i] = make_float4(x, y, z, 0.5f * (x * x + y * y + z * z));
    }
    __syncthreads();

    const float* ax = A + (size_t)b * 3 * N;
    int nb = ytile * (TPB * NPT) + threadIdx.x;

    float px[NPT], py[NPT], pz[NPT], best[NPT];
    int bm[NPT];
#pragma unroll
    for (int k = 0; k < NPT; ++k) {
        int n = nb + k * TPB;
        px[k] = ax[n]; py[k] = ax[N + n]; pz[k] = ax[2 * N + n];
        best[k] = 3.402823466e38f; bm[k] = 0;
    }

#pragma unroll 4
    for (int i = 0; i < NM; ++i) {
        float4 q = sB[i];
#pragma unroll
        for (int k = 0; k < NPT; ++k) {
            float s = fmaf(-px[k], q.x, q.w);
            s = fmaf(-py[k], q.y, s);
            s = fmaf(-pz[k], q.z, s);
            if (s < best[k]) { best[k] = s; bm[k] = i; }
        }
    }

#pragma unroll
    for (int k = 0; k < NPT; ++k) {
        int n = nb + k * TPB;
        unsigned u = __float_as_uint(best[k]);
        u = (u & 0x80000000u) ? ~u : (u | 0x80000000u);   // order-preserving map
        unsigned long long key = ((unsigned long long)u << 32) | (unsigned)(m0 + bm[k]);
        atomicMin(&keys[(size_t)b * N + n], key);
    }
}

// ---------------- cosine body ----------------------------------------------------
// desc layout [B][32][N]; flattened-spatial element (b,n,c) = desc[b,c,n].
template<int N>
__device__ __forceinline__ float cos_body(const float* __restrict__ sd,
                                          const float* __restrict__ td,
                                          const unsigned long long* __restrict__ keys,
                                          int b, int xb)
{
    int n = xb * TPB + threadIdx.x;
    int m = (int)(unsigned)(keys[(size_t)b * N + n] & 0xFFFFFFFFull);

    const float* s = sd + (size_t)b * 32 * N;
    const float* t = td + (size_t)b * 32 * N;
    float dot = 0.f, ns = 0.f, ng = 0.f;
#pragma unroll
    for (int c = 0; c < 32; ++c) {
        float x = s[(size_t)c * N + n];
        float y = t[(size_t)c * N + m];
        dot = fmaf(x, y, dot);
        ns  = fmaf(x, x, ns);
        ng  = fmaf(y, y, ng);
    }
    return dot / (fmaxf(sqrtf(ns), 1e-8f) * fmaxf(sqrtf(ng), 1e-8f));
}

// ---------------- the single persistent kernel ----------------------------------
__global__ void __launch_bounds__(TPB, 4)
mega_kernel(const float* __restrict__ cs,  const float* __restrict__ ct,
            const float* __restrict__ sd0, const float* __restrict__ td0,
            const float* __restrict__ sd1, const float* __restrict__ td1,
            float* __restrict__ out)
{
    __shared__ float4 sB[128];
    __shared__ float wsum[TPB / 32];
    const int gid = blockIdx.x * TPB + threadIdx.x;

    // ---- phase 0: init keys / accumulators ----
    for (int i = gid; i < 16384; i += GT) g_k0[i] = ~0ULL;
    for (int i = gid; i < 2048;  i += GT) g_k1[i] = ~0ULL;
    if (gid < 2) g_acc[gid] = 0.0;

    // ---- phase 1: resize pass 1 (innermost dim), stage0 (R=4) + stage1 (R=8) ----
    {
        const int S0 = 786432, S1 = 393216;          // per tensor
        for (int idx = gid; idx < 2 * S0 + 2 * S1; idx += GT) {
            if (idx < 2 * S0) {
                int tensor = idx / S0, l = idx - tensor * S0;
                resize_elem(tensor ? ct : cs, g_t0A[tensor], 16, 1, 4.f, 0.25f, l);
            } else {
                int r = idx - 2 * S0;
                int tensor = r / S1, l = r - tensor * S1;
                resize_elem(tensor ? ct : cs, g_t1A[tensor], 8, 1, 8.f, 0.125f, l);
            }
        }
    }
    grid_sync();

    // ---- phase 2: resize pass 2 ----
    {
        const int S0 = 196608, S1 = 49152;
        for (int idx = gid; idx < 2 * S0 + 2 * S1; idx += GT) {
            if (idx < 2 * S0) {
                int tensor = idx / S0, l = idx - tensor * S0;
                resize_elem(g_t0A[tensor], g_t0B[tensor], 16, 16, 4.f, 0.25f, l);
            } else {
                int r = idx - 2 * S0;
                int tensor = r / S1, l = r - tensor * S1;
                resize_elem(g_t1A[tensor], g_t1B[tensor], 8, 8, 8.f, 0.125f, l);
            }
        }
    }
    grid_sync();

    // ---- phase 3: resize pass 3 ----
    {
        const int S0 = 49152, S1 = 6144;
        for (int idx = gid; idx < 2 * S0 + 2 * S1; idx += GT) {
            if (idx < 2 * S0) {
                int tensor = idx / S0, l = idx - tensor * S0;
                resize_elem(g_t0B[tensor], g_r0[tensor], 16, 256, 4.f, 0.25f, l);
            } else {
                int r = idx - 2 * S0;
                int tensor = r / S1, l = r - tensor * S1;
                resize_elem(g_t1B[tensor], g_r1[tensor], 8, 64, 8.f, 0.125f, l);
            }
        }
    }
    grid_sync();

    // ---- phase 4: nearest neighbor ----
    // stage0: 512 units = b(4) x ytile(4) x mtile(32), Nm=128, NPT=4
    // stage1: 32 units  = b(4) x mtile(8),             Nm=64,  NPT=2
    {
        int u = blockIdx.x;
        if (u < 512) {
            nn_unit<4096, 4, 128>(g_r0[0], g_r0[1], g_k0,
                                  u & 3, (u >> 2) & 3, u >> 4, sB);
        } else if (u < 544) {
            int v = u - 512;
            nn_unit<512, 2, 64>(g_r1[0], g_r1[1], g_k1,
                                v & 3, 0, v >> 2, sB);
        }
    }
    grid_sync();

    // ---- phase 5: cosine + reduction ----
    // stage0: 64 units = b(4) x xb(16); stage1: 8 units = b(4) x xb(2)
    {
        int u = blockIdx.x;
        if (u < 72) {
            int stage = (u < 64) ? 0 : 1;
            float cv;
            if (stage == 0) cv = cos_body<4096>(sd0, td0, g_k0, u & 3, u >> 2);
            else            cv = cos_body<512> (sd1, td1, g_k1, (u - 64) & 3, (u - 64) >> 2);

            for (int o = 16; o > 0; o >>= 1) cv += __shfl_down_sync(0xffffffffu, cv, o);
            if ((threadIdx.x & 31) == 0) wsum[threadIdx.x >> 5] = cv;
            __syncthreads();
            if (threadIdx.x < TPB / 32) {
                float v = wsum[threadIdx.x];
                for (int o = (TPB / 64); o > 0; o >>= 1) v += __shfl_down_sync(0xffu, v, o);
                if (threadIdx.x == 0) atomicAdd(&g_acc[stage], (double)v);
            }
        }
    }
    grid_sync();

    // ---- phase 6: finalize ----
    if (gid == 0) {
        double l0 = 1.0 - g_acc[0] / (4.0 * 4096.0);
        double l1 = 1.0 - g_acc[1] / (4.0 * 512.0);
        out[0] = (float)(0.5 * (l0 + l1));
    }
}

// ---------------- launch (single kernel launch) ----------------------------------
extern "C" void kernel_launch(void* const* d_in, const int* in_sizes, int n_in,
                              void* d_out, int out_size)
{
    const float* cs  = (const float*)d_in[0];  // canonical_source [4,3,64,64,64]
    const float* ct  = (const float*)d_in[1];  // canonical_target
    const float* sd0 = (const float*)d_in[2];  // src_desc0 [4,32,16,16,16]
    const float* td0 = (const float*)d_in[3];
    const float* sd1 = (const float*)d_in[4];  // src_desc1 [4,32,8,8,8]
    const float* td1 = (const float*)d_in[5];
    float* out = (float*)d_out;

    mega_kernel<<<NBLK, TPB>>>(cs, ct, sd0, td0, sd1, td1, out);
}